// round 2
// baseline (speedup 1.0000x reference)
#include <cuda_runtime.h>

#define FULL 0xffffffffu
#define NQ 8

// Precomputed gate matrices: [branch(3)][gate(16)][U00,U01,U10,U11] complex
__device__ float2 g_gates[3 * 16 * 4];

static __device__ __forceinline__ float2 cmul(float2 a, float2 b) {
    return make_float2(fmaf(a.x, b.x, -a.y * b.y), fmaf(a.x, b.y, a.y * b.x));
}
static __device__ __forceinline__ float2 cmadd(float2 a, float2 b, float2 acc) {
    acc.x = fmaf(a.x, b.x, fmaf(-a.y, b.y, acc.x));
    acc.y = fmaf(a.x, b.y, fmaf(a.y, b.x, acc.y));
    return acc;
}

// ---------------------------------------------------------------------------
// Kernel 1: build all 48 gate matrices (params are batch-uniform scalars).
// Gate order per branch (local bits: j2=q3, j1=q5, j0=q7; lane bits:
// l4=q0, l3=q1, l2=q2, l1=q4, l0=q6):
//  k0..k6  : CR pairs1 (0,1)(2,3)(4,5)(6,7)(1,2)(3,4)(5,6)  -> crp[0..6]
//  k7..k10 : U3 on wires 1,3,5,7                            -> u3p[0..3]
//  k11..k13: CR pairs2 (1,3)(5,7)(3,5)                      -> crp[7..9]
//  k14,k15 : U3 on 3, U3 on 7                               -> u3p[4],u3p[5]
// ---------------------------------------------------------------------------
__global__ void qcnn_precompute(const float* __restrict__ crx, const float* __restrict__ u3x,
                                const float* __restrict__ cry, const float* __restrict__ u3y,
                                const float* __restrict__ crz, const float* __restrict__ u3z) {
    int t = threadIdx.x;
    if (t >= 48) return;
    int br = t >> 4;
    int k  = t & 15;
    const float* crp = (br == 0) ? crx : (br == 1) ? cry : crz;
    const float* u3p = (br == 0) ? u3x : (br == 1) ? u3y : u3z;

    bool isCR;
    int pidx;
    if (k < 7)       { isCR = true;  pidx = k; }
    else if (k < 11) { isCR = false; pidx = k - 7; }
    else if (k < 14) { isCR = true;  pidx = 7 + (k - 11); }
    else             { isCR = false; pidx = 4 + (k - 14); }

    float2 U[4];
    if (isCR) {
        float th = crp[pidx];
        float s, c;
        sincosf(0.5f * th, &s, &c);
        if (br == 0) {            // RX
            U[0] = make_float2(c, 0.f);  U[1] = make_float2(0.f, -s);
            U[2] = make_float2(0.f, -s); U[3] = make_float2(c, 0.f);
        } else if (br == 1) {     // RY
            U[0] = make_float2(c, 0.f);  U[1] = make_float2(-s, 0.f);
            U[2] = make_float2(s, 0.f);  U[3] = make_float2(c, 0.f);
        } else {                  // RZ: diag(e^{-it/2}, e^{it/2})
            U[0] = make_float2(c, -s);   U[1] = make_float2(0.f, 0.f);
            U[2] = make_float2(0.f, 0.f); U[3] = make_float2(c, s);
        }
    } else {
        float th = u3p[pidx * 3 + 0];
        float ph = u3p[pidx * 3 + 1];
        float lm = u3p[pidx * 3 + 2];
        float st, ct, sp, cp, sl, cl, spl, cpl;
        sincosf(0.5f * th, &st, &ct);
        sincosf(ph, &sp, &cp);
        sincosf(lm, &sl, &cl);
        sincosf(ph + lm, &spl, &cpl);
        U[0] = make_float2(ct, 0.f);
        U[1] = make_float2(-cl * st, -sl * st);
        U[2] = make_float2(cp * st, sp * st);
        U[3] = make_float2(cpl * ct, spl * ct);
    }
    float2* dst = &g_gates[(br * 16 + k) * 4];
    dst[0] = U[0]; dst[1] = U[1]; dst[2] = U[2]; dst[3] = U[3];
}

// ---------------------------------------------------------------------------
// Gate helpers.
// ---------------------------------------------------------------------------

// 1q gate on a local bit (register pairs). tm = target bit mask of j,
// jctrl = local-control bits that must be 1, laneok = lane-control predicate.
static __device__ __forceinline__ void gate_local(float2 s[8], const float2* __restrict__ U,
                                                  int tm, int jctrl, bool laneok) {
    if (!laneok) return;
#pragma unroll
    for (int j = 0; j < 8; j++) {
        if (j & tm) continue;
        if ((j & jctrl) != jctrl) continue;
        int j1 = j | tm;
        float2 a0 = s[j], a1 = s[j1];
        s[j]  = cmadd(U[1], a1, cmul(U[0], a0));
        s[j1] = cmadd(U[3], a1, cmul(U[2], a0));
    }
}

// 1q gate on a lane bit (shuffle pairs). lm = lane bit mask,
// ctrl_lane = lane-control predicate, jctrl = local-control bits.
static __device__ __forceinline__ void gate_lane(float2 s[8], const float2* __restrict__ U,
                                                 unsigned lm, bool ctrl_lane, int jctrl, int lane) {
    bool hi = (lane & lm) != 0;
    float2 u0 = hi ? U[2] : U[0];
    float2 u1 = hi ? U[3] : U[1];
#pragma unroll
    for (int j = 0; j < 8; j++) {
        float px = __shfl_xor_sync(FULL, s[j].x, lm);
        float py = __shfl_xor_sync(FULL, s[j].y, lm);
        float2 p = make_float2(px, py);
        float2 a0 = hi ? p : s[j];
        float2 a1 = hi ? s[j] : p;
        float2 n = cmadd(u1, a1, cmul(u0, a0));
        if (ctrl_lane && ((j & jctrl) == jctrl)) s[j] = n;
    }
}

// ---------------------------------------------------------------------------
// Kernel 2: one warp per batch element.
// Layout: local bits j2=q3, j1=q5, j0=q7; lane bits l4=q0,l3=q1,l2=q2,l1=q4,l0=q6.
// ---------------------------------------------------------------------------
__global__ void __launch_bounds__(256) qcnn_main(const float* __restrict__ x,
                                                 const float* __restrict__ w1,
                                                 const float* __restrict__ b1,
                                                 const float* __restrict__ w2,
                                                 const float* __restrict__ b2,
                                                 float* __restrict__ out, int batch) {
    __shared__ float2 smg[192];   // gate matrices
    __shared__ float  smw1[72];
    __shared__ float  smb1[12];
    __shared__ float  smw2[12];
    __shared__ float  smb2;

    for (int i = threadIdx.x; i < 192; i += blockDim.x) smg[i] = g_gates[i];
    for (int i = threadIdx.x; i < 72; i += blockDim.x) smw1[i] = w1[i];
    if (threadIdx.x < 12) { smb1[threadIdx.x] = b1[threadIdx.x]; smw2[threadIdx.x] = w2[threadIdx.x]; }
    if (threadIdx.x == 0) smb2 = b2[0];
    __syncthreads();

    int warp = (blockIdx.x * blockDim.x + threadIdx.x) >> 5;
    int lane = threadIdx.x & 31;
    if (warp >= batch) return;

    // ---- encode: product state -------------------------------------------
    float xv = 0.f;
    if (lane < 8) xv = x[warp * 8 + lane];
    float sv, cv;
    sincosf(0.5f * xv, &sv, &cv);
    float cq[8], sq[8];
#pragma unroll
    for (int q = 0; q < 8; q++) {
        cq[q] = __shfl_sync(FULL, cv, q);
        sq[q] = __shfl_sync(FULL, sv, q);
    }
    float A = (((lane >> 4) & 1) ? sq[0] : cq[0])
            * (((lane >> 3) & 1) ? sq[1] : cq[1])
            * (((lane >> 2) & 1) ? sq[2] : cq[2])
            * (((lane >> 1) & 1) ? sq[4] : cq[4])
            * (((lane     ) & 1) ? sq[6] : cq[6]);
    float init[8];
#pragma unroll
    for (int j = 0; j < 8; j++) {
        init[j] = A * (((j >> 2) & 1) ? sq[3] : cq[3])
                    * (((j >> 1) & 1) ? sq[5] : cq[5])
                    * (((j     ) & 1) ? sq[7] : cq[7]);
    }

    float feats[6];

#pragma unroll 1
    for (int br = 0; br < 3; br++) {
        float2 s[8];
#pragma unroll
        for (int j = 0; j < 8; j++) s[j] = make_float2(init[j], 0.f);
        const float2* G = &smg[br * 64];

        // CR_PAIRS_1
        gate_lane (s, G + 0,  8u, (lane & 16) != 0, 0, lane);   // CR(0,1): c=q0(l4), t=q1(l3)
        gate_local(s, G + 4,  4,  0, (lane & 4) != 0);          // CR(2,3): c=q2(l2), t=q3(j2)
        gate_local(s, G + 8,  2,  0, (lane & 2) != 0);          // CR(4,5): c=q4(l1), t=q5(j1)
        gate_local(s, G + 12, 1,  0, (lane & 1) != 0);          // CR(6,7): c=q6(l0), t=q7(j0)
        gate_lane (s, G + 16, 4u, (lane & 8) != 0, 0, lane);    // CR(1,2): c=q1(l3), t=q2(l2)
        gate_lane (s, G + 20, 2u, true, 4, lane);               // CR(3,4): c=q3(j2), t=q4(l1)
        gate_lane (s, G + 24, 1u, true, 2, lane);               // CR(5,6): c=q5(j1), t=q6(l0)
        // U3 on 1,3,5,7
        gate_lane (s, G + 28, 8u, true, 0, lane);               // U3(1)  q1(l3)
        gate_local(s, G + 32, 4,  0, true);                     // U3(3)  q3(j2)
        gate_local(s, G + 36, 2,  0, true);                     // U3(5)  q5(j1)
        gate_local(s, G + 40, 1,  0, true);                     // U3(7)  q7(j0)
        // CR_PAIRS_2
        gate_local(s, G + 44, 4,  0, (lane & 8) != 0);          // CR(1,3): c=q1(l3), t=q3(j2)
        gate_local(s, G + 48, 1,  2, true);                     // CR(5,7): c=q5(j1), t=q7(j0)
        gate_local(s, G + 52, 2,  4, true);                     // CR(3,5): c=q3(j2), t=q5(j1)
        // final U3 on 3 and 7
        gate_local(s, G + 56, 4,  0, true);                     // U3(3)
        gate_local(s, G + 60, 1,  0, true);                     // U3(7)

        // expectation values <Z> on q3 (j bit2) and q7 (j bit0)
        float e3 = 0.f, e7 = 0.f;
#pragma unroll
        for (int j = 0; j < 8; j++) {
            float p = fmaf(s[j].x, s[j].x, s[j].y * s[j].y);
            e3 += (j & 4) ? -p : p;
            e7 += (j & 1) ? -p : p;
        }
#pragma unroll
        for (int o = 16; o > 0; o >>= 1) {
            e3 += __shfl_xor_sync(FULL, e3, o);
            e7 += __shfl_xor_sync(FULL, e7, o);
        }
        feats[2 * br + 0] = e3;
        feats[2 * br + 1] = e7;
    }

    // ---- MLP: lanes 0..11 each compute one hidden unit, then warp-reduce ---
    float term = 0.f;
    if (lane < 12) {
        float z = smb1[lane];
#pragma unroll
        for (int j = 0; j < 6; j++) z = fmaf(smw1[lane * 6 + j], feats[j], z);
        term = smw2[lane] * tanhf(z);
    }
#pragma unroll
    for (int o = 16; o > 0; o >>= 1) term += __shfl_xor_sync(FULL, term, o);
    if (lane == 0) {
        float z2 = smb2 + term;
        out[warp] = 1.f / (1.f + expf(-z2));
    }
}

extern "C" void kernel_launch(void* const* d_in, const int* in_sizes, int n_in,
                              void* d_out, int out_size) {
    const float* x   = (const float*)d_in[0];
    const float* crx = (const float*)d_in[1];
    const float* u3x = (const float*)d_in[2];
    const float* cry = (const float*)d_in[3];
    const float* u3y = (const float*)d_in[4];
    const float* crz = (const float*)d_in[5];
    const float* u3z = (const float*)d_in[6];
    const float* w1  = (const float*)d_in[7];
    const float* b1  = (const float*)d_in[8];
    const float* w2  = (const float*)d_in[9];
    const float* b2  = (const float*)d_in[10];
    float* out = (float*)d_out;

    int batch = in_sizes[0] / NQ;

    qcnn_precompute<<<1, 64>>>(crx, u3x, cry, u3y, crz, u3z);

    int threads = 256;                       // 8 warps per block
    int blocks = (batch * 32 + threads - 1) / threads;
    qcnn_main<<<blocks, threads>>>(x, w1, b1, w2, b2, out, batch);
}

// round 3
// speedup vs baseline: 1.5826x; 1.5826x over previous
#include <cuda_runtime.h>

#define FULL 0xffffffffu
#define NQ 8

// ---------------------------------------------------------------------------
// Precomputed batch-uniform circuit constants
// ---------------------------------------------------------------------------
__device__ float2 g_cr[2][10];      // branch 0=RX,1=RY: (cos(t/2), sin(t/2))
__device__ float  g_hz[10];         // RZ half-angles t/2
__device__ float2 g_u3[3][6][4];    // full U3 matrices [br][gate][U00,U01,U10,U11]

static __device__ __forceinline__ float2 cmul(float2 a, float2 b) {
    return make_float2(fmaf(a.x, b.x, -a.y * b.y), fmaf(a.x, b.y, a.y * b.x));
}
static __device__ __forceinline__ float2 cmadd(float2 a, float2 b, float2 acc) {
    acc.x = fmaf(a.x, b.x, fmaf(-a.y, b.y, acc.x));
    acc.y = fmaf(a.x, b.y, fmaf(a.y, b.x, acc.y));
    return acc;
}

// ---------------------------------------------------------------------------
// Kernel 1: build gate constants (48 tiny jobs, runs once per launch)
// ---------------------------------------------------------------------------
__global__ void qcnn_precompute(const float* __restrict__ crx, const float* __restrict__ u3x,
                                const float* __restrict__ cry, const float* __restrict__ u3y,
                                const float* __restrict__ crz, const float* __restrict__ u3z) {
    int t = threadIdx.x;
    if (t < 20) {
        int br = t / 10, k = t % 10;
        const float* p = br ? cry : crx;
        float s, c; sincosf(0.5f * p[k], &s, &c);
        g_cr[br][k] = make_float2(c, s);
    } else if (t < 30) {
        g_hz[t - 20] = 0.5f * crz[t - 20];
    } else if (t >= 32 && t < 50) {
        int i = t - 32;
        int br = i / 6, k = i % 6;
        const float* u3p = (br == 0) ? u3x : (br == 1) ? u3y : u3z;
        float th = u3p[k * 3 + 0];
        float ph = u3p[k * 3 + 1];
        float lm = u3p[k * 3 + 2];
        float st, ct, sp, cp, sl, cl, spl, cpl;
        sincosf(0.5f * th, &st, &ct);
        sincosf(ph, &sp, &cp);
        sincosf(lm, &sl, &cl);
        sincosf(ph + lm, &spl, &cpl);
        g_u3[br][k][0] = make_float2(ct, 0.f);
        g_u3[br][k][1] = make_float2(-cl * st, -sl * st);
        g_u3[br][k][2] = make_float2(cp * st, sp * st);
        g_u3[br][k][3] = make_float2(cpl * ct, spl * ct);
    }
}

// ---------------------------------------------------------------------------
// Gate primitives.
// Bit layout: lane bits l4=q0(16) l3=q1(8) l2=q2(4) l1=q4(2) l0=q6(1);
// local bits  j2=q3(4) j1=q5(2) j0=q7(1).
// ---------------------------------------------------------------------------

// Full U3 on a lane bit (diag/offdiag coeffs hoisted — no per-j selects)
static __device__ __forceinline__ void u3_lane(float2 s[8], const float2* __restrict__ U,
                                               unsigned lm, int lane) {
    bool hi = (lane & lm) != 0;
    float2 ud = hi ? U[3] : U[0];
    float2 uo = hi ? U[2] : U[1];
#pragma unroll
    for (int j = 0; j < 8; j++) {
        float px = __shfl_xor_sync(FULL, s[j].x, lm);
        float py = __shfl_xor_sync(FULL, s[j].y, lm);
        s[j] = cmadd(uo, make_float2(px, py), cmul(ud, s[j]));
    }
}

// Full U3 on a lane bit with REAL input state (1 shfl, 4 fl per amp)
static __device__ __forceinline__ void u3_lane_real(const float r[8], float2 s[8],
                                                    const float2* __restrict__ U,
                                                    unsigned lm, int lane) {
    bool hi = (lane & lm) != 0;
    float2 ud = hi ? U[3] : U[0];
    float2 uo = hi ? U[2] : U[1];
#pragma unroll
    for (int j = 0; j < 8; j++) {
        float p = __shfl_xor_sync(FULL, r[j], lm);
        s[j].x = fmaf(ud.x, r[j], uo.x * p);
        s[j].y = fmaf(ud.y, r[j], uo.y * p);
    }
}

// Full U3 on a local bit
static __device__ __forceinline__ void u3_local(float2 s[8], const float2* __restrict__ U, int tm) {
#pragma unroll
    for (int j = 0; j < 8; j++) {
        if (j & tm) continue;
        int j1 = j | tm;
        float2 a0 = s[j], a1 = s[j1];
        s[j]  = cmadd(U[1], a1, cmul(U[0], a0));
        s[j1] = cmadd(U[3], a1, cmul(U[2], a0));
    }
}

// ---- CRX: matrix [[c,-is],[-is,c]] — symmetric update, 4 FMA per amp ------
static __device__ __forceinline__ void crx_lane(float2 s[8], float c, float sv,
                                                unsigned lm, bool cl, int jc) {
#pragma unroll
    for (int j = 0; j < 8; j++) {
        float px = __shfl_xor_sync(FULL, s[j].x, lm);
        float py = __shfl_xor_sync(FULL, s[j].y, lm);
        if (cl && ((j & jc) == jc)) {
            s[j].x = fmaf(c, s[j].x,  sv * py);
            s[j].y = fmaf(c, s[j].y, -sv * px);
        }
    }
}
static __device__ __forceinline__ void crx_local(float2 s[8], float c, float sv,
                                                 int tm, bool cl, int jc) {
    if (!cl) return;
#pragma unroll
    for (int j = 0; j < 8; j++) {
        if (j & tm) continue;
        if ((j & jc) != jc) continue;
        int j1 = j | tm;
        float2 a0 = s[j], a1 = s[j1];
        s[j].x  = fmaf(c, a0.x,  sv * a1.y);
        s[j].y  = fmaf(c, a0.y, -sv * a1.x);
        s[j1].x = fmaf(c, a1.x,  sv * a0.y);
        s[j1].y = fmaf(c, a1.y, -sv * a0.x);
    }
}

// ---- CRY: matrix [[c,-s],[s,c]] — real coefficients, 4 FMA per amp --------
static __device__ __forceinline__ void cry_local(float2 s[8], float c, float sv,
                                                 int tm, bool cl, int jc) {
    if (!cl) return;
#pragma unroll
    for (int j = 0; j < 8; j++) {
        if (j & tm) continue;
        if ((j & jc) != jc) continue;
        int j1 = j | tm;
        float2 a0 = s[j], a1 = s[j1];
        s[j].x  = fmaf(c, a0.x, -sv * a1.x);
        s[j].y  = fmaf(c, a0.y, -sv * a1.y);
        s[j1].x = fmaf(c, a1.x,  sv * a0.x);
        s[j1].y = fmaf(c, a1.y,  sv * a0.y);
    }
}
// Real-state versions (pairs1 of the RY branch: state is still purely real)
static __device__ __forceinline__ void cry_lane_r(float r[8], float c, float sv,
                                                  unsigned lm, bool cl, int jc, int lane) {
    float sgn = (lane & lm) ? sv : -sv;
#pragma unroll
    for (int j = 0; j < 8; j++) {
        float p = __shfl_xor_sync(FULL, r[j], lm);
        if (cl && ((j & jc) == jc)) r[j] = fmaf(c, r[j], sgn * p);
    }
}
static __device__ __forceinline__ void cry_local_r(float r[8], float c, float sv,
                                                   int tm, bool cl) {
    if (!cl) return;
#pragma unroll
    for (int j = 0; j < 8; j++) {
        if (j & tm) continue;
        int j1 = j | tm;
        float a0 = r[j], a1 = r[j1];
        r[j]  = fmaf(c, a0, -sv * a1);
        r[j1] = fmaf(c, a1,  sv * a0);
    }
}

// <Z> on q3 (j bit2) and q7 (j bit0), full-warp reduce
static __device__ __forceinline__ void expval2(const float2 s[8], float* e3o, float* e7o) {
    float e3 = 0.f, e7 = 0.f;
#pragma unroll
    for (int j = 0; j < 8; j++) {
        float p = fmaf(s[j].x, s[j].x, s[j].y * s[j].y);
        e3 += (j & 4) ? -p : p;
        e7 += (j & 1) ? -p : p;
    }
#pragma unroll
    for (int o = 16; o > 0; o >>= 1) {
        e3 += __shfl_xor_sync(FULL, e3, o);
        e7 += __shfl_xor_sync(FULL, e7, o);
    }
    *e3o = e3; *e7o = e7;
}

// ---------------------------------------------------------------------------
// Kernel 2: one warp per batch element.
// ---------------------------------------------------------------------------
__global__ void __launch_bounds__(256) qcnn_main(const float* __restrict__ x,
                                                 const float* __restrict__ w1,
                                                 const float* __restrict__ b1,
                                                 const float* __restrict__ w2,
                                                 const float* __restrict__ b2,
                                                 float* __restrict__ out, int batch) {
    __shared__ float2 s_u3[3][6][4];   // 72 float2
    __shared__ float2 s_cr[2][10];
    __shared__ float  s_hz[10];
    __shared__ float  smw1[72];
    __shared__ float  smb1[12];
    __shared__ float  smw2[12];
    __shared__ float  smb2;

    {
        float2* su3f = &s_u3[0][0][0];
        const float2* gu3f = &g_u3[0][0][0];
        for (int i = threadIdx.x; i < 72; i += blockDim.x) su3f[i] = gu3f[i];
        for (int i = threadIdx.x; i < 72; i += blockDim.x) smw1[i] = w1[i];
        if (threadIdx.x < 20) ((float2*)s_cr)[threadIdx.x] = ((const float2*)g_cr)[threadIdx.x];
        if (threadIdx.x >= 32 && threadIdx.x < 42) s_hz[threadIdx.x - 32] = g_hz[threadIdx.x - 32];
        if (threadIdx.x >= 64 && threadIdx.x < 76) {
            smb1[threadIdx.x - 64] = b1[threadIdx.x - 64];
            smw2[threadIdx.x - 64] = w2[threadIdx.x - 64];
        }
        if (threadIdx.x == 0) smb2 = b2[0];
    }
    __syncthreads();

    int warp = (blockIdx.x * blockDim.x + threadIdx.x) >> 5;
    int lane = threadIdx.x & 31;
    if (warp >= batch) return;

    // ---- encode: product state -------------------------------------------
    float xv = 0.f;
    if (lane < 8) xv = x[warp * 8 + lane];
    float sv0, cv0;
    __sincosf(0.5f * xv, &sv0, &cv0);
    float cq[8], sq[8];
#pragma unroll
    for (int q = 0; q < 8; q++) {
        cq[q] = __shfl_sync(FULL, cv0, q);
        sq[q] = __shfl_sync(FULL, sv0, q);
    }
    float A = ((lane & 16) ? sq[0] : cq[0])
            * ((lane &  8) ? sq[1] : cq[1])
            * ((lane &  4) ? sq[2] : cq[2])
            * ((lane &  2) ? sq[4] : cq[4])
            * ((lane &  1) ? sq[6] : cq[6]);
    float init[8];
#pragma unroll
    for (int j = 0; j < 8; j++) {
        init[j] = A * ((j & 4) ? sq[3] : cq[3])
                    * ((j & 2) ? sq[5] : cq[5])
                    * ((j & 1) ? sq[7] : cq[7]);
    }

    float feats[6];

    // ================= RX branch =================
    {
        const float2* cr = s_cr[0];
        float2 s[8];
        // cr0 (0,1): ctrl l4, target l3 — real input state
        {
            float c = cr[0].x, sv = cr[0].y;
            bool cl = (lane & 16) != 0;
#pragma unroll
            for (int j = 0; j < 8; j++) {
                float p = __shfl_xor_sync(FULL, init[j], 8);
                s[j].x = cl ? c * init[j] : init[j];
                s[j].y = cl ? -sv * p : 0.f;
            }
        }
        crx_local(s, cr[1].x, cr[1].y, 4, (lane & 4) != 0, 0);  // CR(2,3)
        crx_local(s, cr[2].x, cr[2].y, 2, (lane & 2) != 0, 0);  // CR(4,5)
        crx_local(s, cr[3].x, cr[3].y, 1, (lane & 1) != 0, 0);  // CR(6,7)
        crx_lane (s, cr[4].x, cr[4].y, 4u, (lane & 8) != 0, 0); // CR(1,2)
        crx_lane (s, cr[5].x, cr[5].y, 2u, true, 4);            // CR(3,4)
        crx_lane (s, cr[6].x, cr[6].y, 1u, true, 2);            // CR(5,6)
        u3_lane (s, s_u3[0][0], 8u, lane);                      // U3(1)
        u3_local(s, s_u3[0][1], 4);                             // U3(3)
        u3_local(s, s_u3[0][2], 2);                             // U3(5)
        u3_local(s, s_u3[0][3], 1);                             // U3(7)
        crx_local(s, cr[7].x, cr[7].y, 4, (lane & 8) != 0, 0);  // CR(1,3)
        crx_local(s, cr[8].x, cr[8].y, 1, true, 2);             // CR(5,7)
        crx_local(s, cr[9].x, cr[9].y, 2, true, 4);             // CR(3,5)
        u3_local(s, s_u3[0][4], 4);                             // U3(3)
        u3_local(s, s_u3[0][5], 1);                             // U3(7)
        expval2(s, &feats[0], &feats[1]);
    }

    // ================= RY branch (pairs1 fully real) =================
    {
        const float2* cr = s_cr[1];
        float r[8];
#pragma unroll
        for (int j = 0; j < 8; j++) r[j] = init[j];
        cry_lane_r (r, cr[0].x, cr[0].y, 8u, (lane & 16) != 0, 0, lane); // CR(0,1)
        cry_local_r(r, cr[1].x, cr[1].y, 4, (lane & 4) != 0);            // CR(2,3)
        cry_local_r(r, cr[2].x, cr[2].y, 2, (lane & 2) != 0);            // CR(4,5)
        cry_local_r(r, cr[3].x, cr[3].y, 1, (lane & 1) != 0);            // CR(6,7)
        cry_lane_r (r, cr[4].x, cr[4].y, 4u, (lane & 8) != 0, 0, lane);  // CR(1,2)
        cry_lane_r (r, cr[5].x, cr[5].y, 2u, true, 4, lane);             // CR(3,4)
        cry_lane_r (r, cr[6].x, cr[6].y, 1u, true, 2, lane);             // CR(5,6)
        float2 s[8];
        u3_lane_real(r, s, s_u3[1][0], 8u, lane);                        // U3(1)
        u3_local(s, s_u3[1][1], 4);                                      // U3(3)
        u3_local(s, s_u3[1][2], 2);                                      // U3(5)
        u3_local(s, s_u3[1][3], 1);                                      // U3(7)
        cry_local(s, cr[7].x, cr[7].y, 4, (lane & 8) != 0, 0);           // CR(1,3)
        cry_local(s, cr[8].x, cr[8].y, 1, true, 2);                      // CR(5,7)
        cry_local(s, cr[9].x, cr[9].y, 2, true, 4);                      // CR(3,5)
        u3_local(s, s_u3[1][4], 4);                                      // U3(3)
        u3_local(s, s_u3[1][5], 1);                                      // U3(7)
        expval2(s, &feats[2], &feats[3]);
    }

    // ================= RZ branch (CRZ layers fused into phases) ==========
    {
        // pairs1: 7 commuting diagonal gates -> one phase per amplitude
        // gate k contributes ctrl_k * (target_k ? +h_k : -h_k)
        float th_lane = 0.f;
        if (lane & 16) th_lane += (lane & 8) ? s_hz[0] : -s_hz[0];  // CR(0,1)
        if (lane & 8)  th_lane += (lane & 4) ? s_hz[4] : -s_hz[4];  // CR(1,2)
        float t1 = (lane & 4) ? s_hz[1] : 0.f;                      // CR(2,3): tgt j2
        float t2 = (lane & 2) ? s_hz[2] : 0.f;                      // CR(4,5): tgt j1
        float t3 = (lane & 1) ? s_hz[3] : 0.f;                      // CR(6,7): tgt j0
        float u5 = (lane & 2) ? s_hz[5] : -s_hz[5];                 // CR(3,4): ctrl j2
        float u6 = (lane & 1) ? s_hz[6] : -s_hz[6];                 // CR(5,6): ctrl j1
        float2 s[8];
#pragma unroll
        for (int j = 0; j < 8; j++) {
            float th = th_lane
                     + ((j & 4) ? t1 : -t1)
                     + ((j & 2) ? t2 : -t2)
                     + ((j & 1) ? t3 : -t3);
            if (j & 4) th += u5;
            if (j & 2) th += u6;
            float sn, cs;
            __sincosf(th, &sn, &cs);
            s[j].x = init[j] * cs;
            s[j].y = init[j] * sn;
        }
        u3_lane (s, s_u3[2][0], 8u, lane);                          // U3(1)
        u3_local(s, s_u3[2][1], 4);                                 // U3(3)
        u3_local(s, s_u3[2][2], 2);                                 // U3(5)
        u3_local(s, s_u3[2][3], 1);                                 // U3(7)
        // pairs2: 3 commuting diagonal gates -> one phase per amplitude
        float t7 = (lane & 8) ? s_hz[7] : 0.f;                      // CR(1,3)
        float h8 = s_hz[8], h9 = s_hz[9];
#pragma unroll
        for (int j = 0; j < 8; j++) {
            float th = (j & 4) ? t7 : -t7;
            if (j & 2) th += (j & 1) ? h8 : -h8;                    // CR(5,7)
            if (j & 4) th += (j & 2) ? h9 : -h9;                    // CR(3,5)
            float sn, cs;
            __sincosf(th, &sn, &cs);
            float2 a = s[j];
            s[j].x = fmaf(a.x, cs, -a.y * sn);
            s[j].y = fmaf(a.x, sn,  a.y * cs);
        }
        u3_local(s, s_u3[2][4], 4);                                 // U3(3)
        u3_local(s, s_u3[2][5], 1);                                 // U3(7)
        expval2(s, &feats[4], &feats[5]);
    }

    // ---- MLP: lanes 0..11 each compute one hidden unit ---------------------
    float term = 0.f;
    if (lane < 12) {
        float z = smb1[lane];
#pragma unroll
        for (int j = 0; j < 6; j++) z = fmaf(smw1[lane * 6 + j], feats[j], z);
        term = smw2[lane] * tanhf(z);
    }
#pragma unroll
    for (int o = 8; o > 0; o >>= 1) term += __shfl_xor_sync(FULL, term, o);
    if (lane == 0) {
        float z2 = smb2 + term;
        out[warp] = 1.f / (1.f + expf(-z2));
    }
}

extern "C" void kernel_launch(void* const* d_in, const int* in_sizes, int n_in,
                              void* d_out, int out_size) {
    const float* x   = (const float*)d_in[0];
    const float* crx = (const float*)d_in[1];
    const float* u3x = (const float*)d_in[2];
    const float* cry = (const float*)d_in[3];
    const float* u3y = (const float*)d_in[4];
    const float* crz = (const float*)d_in[5];
    const float* u3z = (const float*)d_in[6];
    const float* w1  = (const float*)d_in[7];
    const float* b1  = (const float*)d_in[8];
    const float* w2  = (const float*)d_in[9];
    const float* b2  = (const float*)d_in[10];
    float* out = (float*)d_out;

    int batch = in_sizes[0] / NQ;

    qcnn_precompute<<<1, 64>>>(crx, u3x, cry, u3y, crz, u3z);

    int threads = 256;   // 8 warps per block
    int blocks = (batch * 32 + threads - 1) / threads;
    qcnn_main<<<blocks, threads>>>(x, w1, b1, w2, b2, out, batch);
}

// round 7
// speedup vs baseline: 1.7563x; 1.1098x over previous
#include <cuda_runtime.h>

#define FULL 0xffffffffu
#define NQ 8

// ---------------------------------------------------------------------------
// Globals written by precompute kernel
//   g_mat[br][g][e*2+0] = (E.x, E.x)   g_mat[br][g][e*2+1] = (-E.y, E.y)
//   gates g: 0=U3(1) 1=U3(5) 2=MA0 3=MA1 4=MB0 5=MB1 6=U3(3)' 7=U3(7)'
// ---------------------------------------------------------------------------
__device__ float2 g_mat[3][8][8];
__device__ float2 g_cr[3][10];     // (cos(t/2), sin(t/2)) per branch
__device__ float  g_hz[10];        // RZ half-angles

// ---------------------------------------------------------------------------
// packed f32x2 helpers (FFMA2 — 2 fp32 ops per instruction on sm_103a)
// ---------------------------------------------------------------------------
static __device__ __forceinline__ float2 f2mul(float2 a, float2 b) {
    float2 d;
    asm("{.reg .b64 A,B,D;\n\t"
        "mov.b64 A,{%2,%3};\n\t"
        "mov.b64 B,{%4,%5};\n\t"
        "mul.rn.f32x2 D,A,B;\n\t"
        "mov.b64 {%0,%1},D;}"
        : "=f"(d.x), "=f"(d.y)
        : "f"(a.x), "f"(a.y), "f"(b.x), "f"(b.y));
    return d;
}
static __device__ __forceinline__ float2 f2fma(float2 a, float2 b, float2 c) {
    float2 d;
    asm("{.reg .b64 A,B,C,D;\n\t"
        "mov.b64 A,{%2,%3};\n\t"
        "mov.b64 B,{%4,%5};\n\t"
        "mov.b64 C,{%6,%7};\n\t"
        "fma.rn.f32x2 D,A,B,C;\n\t"
        "mov.b64 {%0,%1},D;}"
        : "=f"(d.x), "=f"(d.y)
        : "f"(a.x), "f"(a.y), "f"(b.x), "f"(b.y), "f"(c.x), "f"(c.y));
    return d;
}
static __device__ __forceinline__ float2 swp(float2 v) { return make_float2(v.y, v.x); }
static __device__ __forceinline__ float2 dup(float x)  { return make_float2(x, x); }

static __device__ __forceinline__ float2 cmul(float2 a, float2 b) {
    return make_float2(fmaf(a.x, b.x, -a.y * b.y), fmaf(a.x, b.y, a.y * b.x));
}

// ---------------------------------------------------------------------------
// Precompute kernel: gate constants + fused matrices, packed-dup format
// ---------------------------------------------------------------------------
__global__ void qcnn_precompute(const float* __restrict__ crx, const float* __restrict__ u3x,
                                const float* __restrict__ cry, const float* __restrict__ u3y,
                                const float* __restrict__ crz, const float* __restrict__ u3z) {
    __shared__ float2 su3[3][6][4];
    __shared__ float2 scr[3][10];
    int t = threadIdx.x;
    if (t < 30) {
        int br = t / 10, k = t % 10;
        const float* p = (br == 0) ? crx : (br == 1) ? cry : crz;
        float s, c; sincosf(0.5f * p[k], &s, &c);
        scr[br][k] = make_float2(c, s);
        g_cr[br][k] = make_float2(c, s);
        if (br == 2) g_hz[k] = 0.5f * crz[k];
    }
    if (t >= 32 && t < 50) {
        int i = t - 32, br = i / 6, k = i % 6;
        const float* u3p = (br == 0) ? u3x : (br == 1) ? u3y : u3z;
        float th = u3p[k*3+0], ph = u3p[k*3+1], lm = u3p[k*3+2];
        float st, ct, sp, cp, sl, cl, spl, cpl;
        sincosf(0.5f * th, &st, &ct);
        sincosf(ph, &sp, &cp);
        sincosf(lm, &sl, &cl);
        sincosf(ph + lm, &spl, &cpl);
        su3[br][k][0] = make_float2(ct, 0.f);
        su3[br][k][1] = make_float2(-cl * st, -sl * st);
        su3[br][k][2] = make_float2(cp * st, sp * st);
        su3[br][k][3] = make_float2(cpl * ct, spl * ct);
    }
    __syncthreads();
    if (t < 3) {
        int br = t;
        float2 M[8][4];
        for (int e = 0; e < 4; e++) {
            M[0][e] = su3[br][0][e];   // U3(1)
            M[1][e] = su3[br][2][e];   // U3(5)
            M[2][e] = su3[br][1][e];   // MA0 = U3(3)
            M[4][e] = su3[br][3][e];   // MB0 = U3(7)
            M[6][e] = su3[br][4][e];   // U3(3)'
            M[7][e] = su3[br][5][e];   // U3(7)'
        }
        // R matrices for CR params 7 (A) and 8 (B)
        for (int which = 0; which < 2; which++) {
            float2 cs = scr[br][7 + which];
            float2 R[4];
            if (br == 0) {        // RX
                R[0] = make_float2(cs.x, 0.f);  R[1] = make_float2(0.f, -cs.y);
                R[2] = make_float2(0.f, -cs.y); R[3] = make_float2(cs.x, 0.f);
            } else if (br == 1) { // RY
                R[0] = make_float2(cs.x, 0.f);  R[1] = make_float2(-cs.y, 0.f);
                R[2] = make_float2(cs.y, 0.f);  R[3] = make_float2(cs.x, 0.f);
            } else {              // RZ
                R[0] = make_float2(cs.x, -cs.y); R[1] = make_float2(0.f, 0.f);
                R[2] = make_float2(0.f, 0.f);    R[3] = make_float2(cs.x, cs.y);
            }
            const float2* U = (which == 0) ? su3[br][1] : su3[br][3];
            float2* D = M[3 + which * 2];  // M[3]=MA1, M[5]=MB1
            D[0] = make_float2(cmul(R[0],U[0]).x + cmul(R[1],U[2]).x,
                               cmul(R[0],U[0]).y + cmul(R[1],U[2]).y);
            D[1] = make_float2(cmul(R[0],U[1]).x + cmul(R[1],U[3]).x,
                               cmul(R[0],U[1]).y + cmul(R[1],U[3]).y);
            D[2] = make_float2(cmul(R[2],U[0]).x + cmul(R[3],U[2]).x,
                               cmul(R[2],U[0]).y + cmul(R[3],U[2]).y);
            D[3] = make_float2(cmul(R[2],U[1]).x + cmul(R[3],U[3]).x,
                               cmul(R[2],U[1]).y + cmul(R[3],U[3]).y);
        }
        // pack dup'd coefficients
        for (int g = 0; g < 8; g++)
            for (int e = 0; e < 4; e++) {
                float2 E = M[g][e];
                g_mat[br][g][e*2+0] = make_float2(E.x, E.x);
                g_mat[br][g][e*2+1] = make_float2(-E.y, E.y);
            }
    }
}

// ---------------------------------------------------------------------------
// Gate primitives (packed).
// Bit layout: lane bits l4=q0(16) l3=q1(8) l2=q2(4) l1=q4(2) l0=q6(1);
// local bits  j2=q3(4) j1=q5(2) j0=q7(1).
// ---------------------------------------------------------------------------
static __device__ __forceinline__ void mat_pair(const float2* __restrict__ K,
                                                float2& x0, float2& x1) {
    float2 a0 = x0, a1 = x1, a0s = swp(a0), a1s = swp(a1);
    float2 o0 = f2mul(K[0], a0);
    o0 = f2fma(K[1], a0s, o0);
    o0 = f2fma(K[2], a1, o0);
    o0 = f2fma(K[3], a1s, o0);
    float2 o1 = f2mul(K[4], a0);
    o1 = f2fma(K[5], a0s, o1);
    o1 = f2fma(K[6], a1, o1);
    o1 = f2fma(K[7], a1s, o1);
    x0 = o0; x1 = o1;
}

static __device__ __forceinline__ void u3p_local(float2 s[8], const float2* __restrict__ K, int tm) {
#pragma unroll
    for (int j = 0; j < 8; j++) {
        if (j & tm) continue;
        mat_pair(K, s[j], s[j | tm]);
    }
}

static __device__ __forceinline__ void u3p_lane(float2 s[8], const float2* __restrict__ K,
                                                unsigned lm, bool hi) {
    const float2* Kd = K + (hi ? 6 : 0);
    const float2* Ko = K + (hi ? 4 : 2);
#pragma unroll
    for (int j = 0; j < 8; j++) {
        float px = __shfl_xor_sync(FULL, s[j].x, lm);
        float py = __shfl_xor_sync(FULL, s[j].y, lm);
        float2 p = make_float2(px, py);
        float2 o = f2mul(Kd[0], s[j]);
        o = f2fma(Kd[1], swp(s[j]), o);
        o = f2fma(Ko[0], p, o);
        o = f2fma(Ko[1], swp(p), o);
        s[j] = o;
    }
}

// CRX on a lane target: out = dup(c)*s + (s,-s)*(p.y,p.x); only j&jc rows active
static __device__ __forceinline__ void crx_lane_pk(float2 s[8], float2 kc, float2 ks,
                                                   unsigned lm, int jc) {
#pragma unroll
    for (int j = 0; j < 8; j++) {
        if ((j & jc) != jc) continue;
        float px = __shfl_xor_sync(FULL, s[j].x, lm);
        float py = __shfl_xor_sync(FULL, s[j].y, lm);
        float2 o = f2mul(kc, s[j]);
        s[j] = f2fma(ks, make_float2(py, px), o);
    }
}

// CRY on a lane target, REAL packed state rp[k]=(r[2k],r[2k+1]); kreg mask selects j regs
static __device__ __forceinline__ void cry_lane_rp(float2 rp[4], float2 kc, float2 ksgn,
                                                   unsigned lm, int kmask) {
#pragma unroll
    for (int k = 0; k < 4; k++) {
        if ((k & kmask) != kmask) continue;
        float px = __shfl_xor_sync(FULL, rp[k].x, lm);
        float py = __shfl_xor_sync(FULL, rp[k].y, lm);
        rp[k] = f2fma(ksgn, make_float2(px, py), f2mul(kc, rp[k]));
    }
}

static __device__ __forceinline__ void expval2(const float2 s[8], float* e3o, float* e7o) {
    float e3 = 0.f, e7 = 0.f;
#pragma unroll
    for (int j = 0; j < 8; j++) {
        float2 q = f2mul(s[j], s[j]);
        float p = q.x + q.y;
        e3 += (j & 4) ? -p : p;
        e7 += (j & 1) ? -p : p;
    }
#pragma unroll
    for (int o = 16; o > 0; o >>= 1) {
        e3 += __shfl_xor_sync(FULL, e3, o);
        e7 += __shfl_xor_sync(FULL, e7, o);
    }
    *e3o = e3; *e7o = e7;
}

// shared tail per branch: U3(5), A(j2, lane-sel l3), B(j0, j1-sel), then caller
// applies CR(3,5), then U3(3)', U3(7)'
static __device__ __forceinline__ void tail_a_b(float2 s[8], const float2* __restrict__ KM, bool L3) {
    u3p_local(s, KM + 8, 2);                        // U3(5) on j1
    u3p_local(s, KM + 16 + (L3 ? 8 : 0), 4);        // A on j2 (lane-selected)
    mat_pair(KM + 32, s[0], s[1]);                  // B on j0, j1=0
    mat_pair(KM + 40, s[2], s[3]);                  // j1=1
    mat_pair(KM + 32, s[4], s[5]);
    mat_pair(KM + 40, s[6], s[7]);
}
static __device__ __forceinline__ void tail_final(float2 s[8], const float2* __restrict__ KM) {
    u3p_local(s, KM + 48, 4);                       // U3(3)'
    u3p_local(s, KM + 56, 1);                       // U3(7)'
}

// ---------------------------------------------------------------------------
// Main kernel: one warp per batch element.
// ---------------------------------------------------------------------------
__global__ void __launch_bounds__(256) qcnn_main(const float* __restrict__ x,
                                                 const float* __restrict__ w1,
                                                 const float* __restrict__ b1,
                                                 const float* __restrict__ w2,
                                                 const float* __restrict__ b2,
                                                 float* __restrict__ out, int batch) {
    __shared__ float2 s_mat[3][8][8];   // 192 float2
    __shared__ float2 s_cr[3][10];
    __shared__ float  s_hz[8];
    __shared__ float  smw1[72];
    __shared__ float  smb1[12];
    __shared__ float  smw2[12];
    __shared__ float  smb2;

    {
        float2* d = &s_mat[0][0][0];
        const float2* g = &g_mat[0][0][0];
        for (int i = threadIdx.x; i < 192; i += blockDim.x) d[i] = g[i];
        for (int i = threadIdx.x; i < 72; i += blockDim.x) smw1[i] = w1[i];
        if (threadIdx.x < 30) ((float2*)s_cr)[threadIdx.x] = ((const float2*)g_cr)[threadIdx.x];
        if (threadIdx.x >= 32 && threadIdx.x < 39) s_hz[threadIdx.x - 32] = g_hz[threadIdx.x - 32];
        if (threadIdx.x >= 64 && threadIdx.x < 76) {
            smb1[threadIdx.x - 64] = b1[threadIdx.x - 64];
            smw2[threadIdx.x - 64] = w2[threadIdx.x - 64];
        }
        if (threadIdx.x == 0) smb2 = b2[0];
    }
    __syncthreads();

    int warp = (blockIdx.x * blockDim.x + threadIdx.x) >> 5;
    int lane = threadIdx.x & 31;
    if (warp >= batch) return;

    bool L4 = (lane & 16) != 0, L3 = (lane & 8) != 0, L2 = (lane & 4) != 0,
         L1 = (lane & 2) != 0,  L0 = (lane & 1) != 0;

    // ---- per-qubit (cos, sin) broadcast -----------------------------------
    float xv = 0.f;
    if (lane < 8) xv = x[warp * 8 + lane];
    float sv0, cv0;
    __sincosf(0.5f * xv, &sv0, &cv0);
    float cq[8], sq[8];
#pragma unroll
    for (int q = 0; q < 8; q++) {
        cq[q] = __shfl_sync(FULL, cv0, q);
        sq[q] = __shfl_sync(FULL, sv0, q);
    }
    float u0 = L4 ? sq[0] : cq[0];
    float u2 = L2 ? sq[2] : cq[2];
    float u4 = L1 ? sq[4] : cq[4];
    float u6 = L0 ? sq[6] : cq[6];
    float a1v = L3 ? sq[1] : cq[1];

    float feats[6];

    // ================= RX branch =================
    {
        const float2* cr = s_cr[0];
        const float2* KM = &s_mat[0][0][0];
        // fused encode + first CR layer (factor products)
        float a1w = L3 ? cq[1] : sq[1];
        float2 f01 = make_float2(u0 * (L4 ? cr[0].x * a1v : a1v),
                                 L4 ? -(u0 * cr[0].y * a1w) : 0.f);
        float cc1 = L2 ? cr[1].x : 1.f, ss1 = L2 ? cr[1].y : 0.f;
        float2 f23a = make_float2(u2 * cc1 * cq[3], -u2 * ss1 * sq[3]);
        float2 f23b = make_float2(u2 * cc1 * sq[3], -u2 * ss1 * cq[3]);
        float cc2 = L1 ? cr[2].x : 1.f, ss2 = L1 ? cr[2].y : 0.f;
        float2 f45a = make_float2(u4 * cc2 * cq[5], -u4 * ss2 * sq[5]);
        float2 f45b = make_float2(u4 * cc2 * sq[5], -u4 * ss2 * cq[5]);
        float cc3 = L0 ? cr[3].x : 1.f, ss3 = L0 ? cr[3].y : 0.f;
        float2 f67a = make_float2(u6 * cc3 * cq[7], -u6 * ss3 * sq[7]);
        float2 f67b = make_float2(u6 * cc3 * sq[7], -u6 * ss3 * cq[7]);
        float2 g0 = cmul(f01, f23a), g1 = cmul(f01, f23b);
        float2 h00 = cmul(f45a, f67a), h01 = cmul(f45a, f67b);
        float2 h10 = cmul(f45b, f67a), h11 = cmul(f45b, f67b);
        float2 s[8];
        {
            float2 kx = dup(g0.x), ky = make_float2(-g0.y, g0.y);
            s[0] = f2fma(ky, swp(h00), f2mul(kx, h00));
            s[1] = f2fma(ky, swp(h01), f2mul(kx, h01));
            s[2] = f2fma(ky, swp(h10), f2mul(kx, h10));
            s[3] = f2fma(ky, swp(h11), f2mul(kx, h11));
            kx = dup(g1.x); ky = make_float2(-g1.y, g1.y);
            s[4] = f2fma(ky, swp(h00), f2mul(kx, h00));
            s[5] = f2fma(ky, swp(h01), f2mul(kx, h01));
            s[6] = f2fma(ky, swp(h10), f2mul(kx, h10));
            s[7] = f2fma(ky, swp(h11), f2mul(kx, h11));
        }
        // remaining pairs1 lane gates
        {
            float cc = L3 ? cr[4].x : 1.f, ss = L3 ? cr[4].y : 0.f;
            crx_lane_pk(s, dup(cc), make_float2(ss, -ss), 4u, 0);   // CR(1,2)
        }
        crx_lane_pk(s, dup(cr[5].x), make_float2(cr[5].y, -cr[5].y), 2u, 4); // CR(3,4)
        crx_lane_pk(s, dup(cr[6].x), make_float2(cr[6].y, -cr[6].y), 1u, 2); // CR(5,6)
        u3p_lane(s, KM, 8u, L3);                                    // U3(1)
        tail_a_b(s, KM, L3);
        // CR(3,5): pairs (4,6),(5,7)
        {
            float2 kc = dup(cr[9].x), ks = make_float2(cr[9].y, -cr[9].y);
            float2 o4 = f2fma(ks, swp(s[6]), f2mul(kc, s[4]));
            float2 o6 = f2fma(ks, swp(s[4]), f2mul(kc, s[6]));
            float2 o5 = f2fma(ks, swp(s[7]), f2mul(kc, s[5]));
            float2 o7 = f2fma(ks, swp(s[5]), f2mul(kc, s[7]));
            s[4] = o4; s[6] = o6; s[5] = o5; s[7] = o7;
        }
        tail_final(s, KM);
        expval2(s, &feats[0], &feats[1]);
    }

    // ================= RY branch (pairs1 fully real) =================
    {
        const float2* cr = s_cr[1];
        const float2* KM = &s_mat[1][0][0];
        // fused encode + first CR layer, real factors
        float r1 = L3 ? fmaf(cr[0].y, cq[1], cr[0].x * sq[1])
                      : fmaf(cr[0].x, cq[1], -cr[0].y * sq[1]);
        float f01r = u0 * (L4 ? r1 : a1v);
        float cc1 = L2 ? cr[1].x : 1.f, ss1 = L2 ? cr[1].y : 0.f;
        float f23r0 = u2 * fmaf(cc1, cq[3], -ss1 * sq[3]);
        float f23r1 = u2 * fmaf(ss1, cq[3],  cc1 * sq[3]);
        float cc2 = L1 ? cr[2].x : 1.f, ss2 = L1 ? cr[2].y : 0.f;
        float f45r0 = u4 * fmaf(cc2, cq[5], -ss2 * sq[5]);
        float f45r1 = u4 * fmaf(ss2, cq[5],  cc2 * sq[5]);
        float cc3 = L0 ? cr[3].x : 1.f, ss3 = L0 ? cr[3].y : 0.f;
        float f67r0 = u6 * fmaf(cc3, cq[7], -ss3 * sq[7]);
        float f67r1 = u6 * fmaf(ss3, cq[7],  cc3 * sq[7]);
        float g0r = f01r * f23r0, g1r = f01r * f23r1;
        float2 hp0 = make_float2(f45r0 * f67r0, f45r0 * f67r1);
        float2 hp1 = make_float2(f45r1 * f67r0, f45r1 * f67r1);
        float2 rp[4];
        rp[0] = f2mul(dup(g0r), hp0);
        rp[1] = f2mul(dup(g0r), hp1);
        rp[2] = f2mul(dup(g1r), hp0);
        rp[3] = f2mul(dup(g1r), hp1);
        // remaining pairs1 lane gates on real packed state
        {
            float cc = L3 ? cr[4].x : 1.f, ss = L3 ? cr[4].y : 0.f;
            cry_lane_rp(rp, dup(cc), dup(L2 ? ss : -ss), 4u, 0);   // CR(1,2)
        }
        cry_lane_rp(rp, dup(cr[5].x), dup(L1 ? cr[5].y : -cr[5].y), 2u, 2); // CR(3,4)
        cry_lane_rp(rp, dup(cr[6].x), dup(L0 ? cr[6].y : -cr[6].y), 1u, 1); // CR(5,6)
        // U3(1) on real state -> complex
        float2 s[8];
        {
            const float2* K = KM;
            int di = L3 ? 3 : 0, oi = L3 ? 2 : 1;
            float2 cd = make_float2(K[di*2].x, K[di*2+1].y);
            float2 co = make_float2(K[oi*2].x, K[oi*2+1].y);
#pragma unroll
            for (int j = 0; j < 8; j++) {
                float r = (j & 1) ? rp[j >> 1].y : rp[j >> 1].x;
                float p = __shfl_xor_sync(FULL, r, 8);
                s[j] = f2fma(co, dup(p), f2mul(cd, dup(r)));
            }
        }
        tail_a_b(s, KM, L3);
        // CR(3,5): real coeffs, pairs (4,6),(5,7)
        {
            float2 kc = dup(cr[9].x), kn = dup(-cr[9].y), kp = dup(cr[9].y);
            float2 o4 = f2fma(kn, s[6], f2mul(kc, s[4]));
            float2 o6 = f2fma(kp, s[4], f2mul(kc, s[6]));
            float2 o5 = f2fma(kn, s[7], f2mul(kc, s[5]));
            float2 o7 = f2fma(kp, s[5], f2mul(kc, s[7]));
            s[4] = o4; s[6] = o6; s[5] = o5; s[7] = o7;
        }
        tail_final(s, KM);
        expval2(s, &feats[2], &feats[3]);
    }

    // ================= RZ branch =================
    {
        const float2* KM = &s_mat[2][0][0];
        // real product init
        float A = u0 * (L3 ? sq[1] : cq[1]) * u2 * u4 * u6;
        float init[8];
#pragma unroll
        for (int j = 0; j < 8; j++) {
            init[j] = A * ((j & 4) ? sq[3] : cq[3])
                        * ((j & 2) ? sq[5] : cq[5])
                        * ((j & 1) ? sq[7] : cq[7]);
        }
        // pairs1: 7 commuting diagonal CRZ -> single phase per amplitude
        float th_lane = 0.f;
        if (lane & 16) th_lane += (lane & 8) ? s_hz[0] : -s_hz[0];  // CR(0,1)
        if (lane & 8)  th_lane += (lane & 4) ? s_hz[4] : -s_hz[4];  // CR(1,2)
        float t1 = L2 ? s_hz[1] : 0.f;                              // CR(2,3)
        float t2 = L1 ? s_hz[2] : 0.f;                              // CR(4,5)
        float t3 = L0 ? s_hz[3] : 0.f;                              // CR(6,7)
        float u5 = L1 ? s_hz[5] : -s_hz[5];                         // CR(3,4)
        float u6z = L0 ? s_hz[6] : -s_hz[6];                        // CR(5,6)
        float2 s[8];
#pragma unroll
        for (int j = 0; j < 8; j++) {
            float th = th_lane
                     + ((j & 4) ? t1 : -t1)
                     + ((j & 2) ? t2 : -t2)
                     + ((j & 1) ? t3 : -t3);
            if (j & 4) th += u5;
            if (j & 2) th += u6z;
            float sn, cs;
            __sincosf(th, &sn, &cs);
            s[j] = f2mul(dup(init[j]), make_float2(cs, sn));
        }
        u3p_lane(s, KM, 8u, L3);                                    // U3(1)
        tail_a_b(s, KM, L3);
        // CR(3,5): diagonal phase: amps 4,5 *= e^{-ih9}; amps 6,7 *= e^{+ih9}
        {
            float2 cs9 = s_cr[2][9];
            float2 kc = dup(cs9.x);
            float2 km = make_float2(cs9.y, -cs9.y);
            float2 kp = make_float2(-cs9.y, cs9.y);
            s[4] = f2fma(km, swp(s[4]), f2mul(kc, s[4]));
            s[5] = f2fma(km, swp(s[5]), f2mul(kc, s[5]));
            s[6] = f2fma(kp, swp(s[6]), f2mul(kc, s[6]));
            s[7] = f2fma(kp, swp(s[7]), f2mul(kc, s[7]));
        }
        tail_final(s, KM);
        expval2(s, &feats[4], &feats[5]);
    }

    // ---- MLP ----------------------------------------------------------------
    float term = 0.f;
    if (lane < 12) {
        float z = smb1[lane];
#pragma unroll
        for (int j = 0; j < 6; j++) z = fmaf(smw1[lane * 6 + j], feats[j], z);
        term = smw2[lane] * tanhf(z);
    }
#pragma unroll
    for (int o = 8; o > 0; o >>= 1) term += __shfl_xor_sync(FULL, term, o);
    if (lane == 0) {
        float z2 = smb2 + term;
        out[warp] = 1.f / (1.f + expf(-z2));
    }
}

extern "C" void kernel_launch(void* const* d_in, const int* in_sizes, int n_in,
                              void* d_out, int out_size) {
    const float* x   = (const float*)d_in[0];
    const float* crx = (const float*)d_in[1];
    const float* u3x = (const float*)d_in[2];
    const float* cry = (const float*)d_in[3];
    const float* u3y = (const float*)d_in[4];
    const float* crz = (const float*)d_in[5];
    const float* u3z = (const float*)d_in[6];
    const float* w1  = (const float*)d_in[7];
    const float* b1  = (const float*)d_in[8];
    const float* w2  = (const float*)d_in[9];
    const float* b2  = (const float*)d_in[10];
    float* out = (float*)d_out;

    int batch = in_sizes[0] / NQ;

    qcnn_precompute<<<1, 64>>>(crx, u3x, cry, u3y, crz, u3z);

    int threads = 256;   // 8 warps per block
    int blocks = (batch * 32 + threads - 1) / threads;
    qcnn_main<<<blocks, threads>>>(x, w1, b1, w2, b2, out, batch);
}

// round 8
// speedup vs baseline: 1.9001x; 1.0819x over previous
#include <cuda_runtime.h>

#define FULL 0xffffffffu
#define NQ 8

// ---------------------------------------------------------------------------
// Globals written by precompute kernel
//   g_mat[br][g][e*2+0] = (E.x, E.x)   g_mat[br][g][e*2+1] = (-E.y, E.y)
//   gates g: 0=U3(1) 1=U3(5) 2=MA0 3=MA1 4=MB0 5=MB1
//   g_obs[br][0] = (a3, 2b3.x, -2b3.y, 0) observable for q3 (U3(3)' folded)
//   g_obs[br][1] = (a7, 2b7.x, -2b7.y, 0) observable for q7 (U3(7)' folded)
// ---------------------------------------------------------------------------
__device__ float2 g_mat[3][6][8];
__device__ float4 g_obs[3][2];
__device__ float2 g_cr[3][10];     // (cos(t/2), sin(t/2)) per branch
__device__ float  g_hz[10];        // RZ half-angles

// ---------------------------------------------------------------------------
// packed f32x2 helpers (FFMA2 — 2 fp32 ops per instruction on sm_103a)
// ---------------------------------------------------------------------------
static __device__ __forceinline__ float2 f2mul(float2 a, float2 b) {
    float2 d;
    asm("{.reg .b64 A,B,D;\n\t"
        "mov.b64 A,{%2,%3};\n\t"
        "mov.b64 B,{%4,%5};\n\t"
        "mul.rn.f32x2 D,A,B;\n\t"
        "mov.b64 {%0,%1},D;}"
        : "=f"(d.x), "=f"(d.y)
        : "f"(a.x), "f"(a.y), "f"(b.x), "f"(b.y));
    return d;
}
static __device__ __forceinline__ float2 f2fma(float2 a, float2 b, float2 c) {
    float2 d;
    asm("{.reg .b64 A,B,C,D;\n\t"
        "mov.b64 A,{%2,%3};\n\t"
        "mov.b64 B,{%4,%5};\n\t"
        "mov.b64 C,{%6,%7};\n\t"
        "fma.rn.f32x2 D,A,B,C;\n\t"
        "mov.b64 {%0,%1},D;}"
        : "=f"(d.x), "=f"(d.y)
        : "f"(a.x), "f"(a.y), "f"(b.x), "f"(b.y), "f"(c.x), "f"(c.y));
    return d;
}
static __device__ __forceinline__ float2 swp(float2 v) { return make_float2(v.y, v.x); }
static __device__ __forceinline__ float2 dup(float x)  { return make_float2(x, x); }

static __device__ __forceinline__ float2 cmul(float2 a, float2 b) {
    return make_float2(fmaf(a.x, b.x, -a.y * b.y), fmaf(a.x, b.y, a.y * b.x));
}
// conj(u) * v
static __device__ __forceinline__ float2 cjmul(float2 u, float2 v) {
    return make_float2(fmaf(u.x, v.x,  u.y * v.y), fmaf(u.x, v.y, -u.y * v.x));
}

// ---------------------------------------------------------------------------
// Precompute kernel: gate constants + fused matrices + folded observables
// ---------------------------------------------------------------------------
__global__ void qcnn_precompute(const float* __restrict__ crx, const float* __restrict__ u3x,
                                const float* __restrict__ cry, const float* __restrict__ u3y,
                                const float* __restrict__ crz, const float* __restrict__ u3z) {
    __shared__ float2 su3[3][6][4];
    __shared__ float2 scr[3][10];
    int t = threadIdx.x;
    if (t < 30) {
        int br = t / 10, k = t % 10;
        const float* p = (br == 0) ? crx : (br == 1) ? cry : crz;
        float s, c; sincosf(0.5f * p[k], &s, &c);
        scr[br][k] = make_float2(c, s);
        g_cr[br][k] = make_float2(c, s);
        if (br == 2) g_hz[k] = 0.5f * crz[k];
    }
    if (t >= 32 && t < 50) {
        int i = t - 32, br = i / 6, k = i % 6;
        const float* u3p = (br == 0) ? u3x : (br == 1) ? u3y : u3z;
        float th = u3p[k*3+0], ph = u3p[k*3+1], lm = u3p[k*3+2];
        float st, ct, sp, cp, sl, cl, spl, cpl;
        sincosf(0.5f * th, &st, &ct);
        sincosf(ph, &sp, &cp);
        sincosf(lm, &sl, &cl);
        sincosf(ph + lm, &spl, &cpl);
        su3[br][k][0] = make_float2(ct, 0.f);
        su3[br][k][1] = make_float2(-cl * st, -sl * st);
        su3[br][k][2] = make_float2(cp * st, sp * st);
        su3[br][k][3] = make_float2(cpl * ct, spl * ct);
    }
    __syncthreads();
    if (t < 3) {
        int br = t;
        float2 M[6][4];
        for (int e = 0; e < 4; e++) {
            M[0][e] = su3[br][0][e];   // U3(1)
            M[1][e] = su3[br][2][e];   // U3(5)
            M[2][e] = su3[br][1][e];   // MA0 = U3(3)
            M[4][e] = su3[br][3][e];   // MB0 = U3(7)
        }
        // R matrices for CR params 7 (A) and 8 (B)
        for (int which = 0; which < 2; which++) {
            float2 cs = scr[br][7 + which];
            float2 R[4];
            if (br == 0) {        // RX
                R[0] = make_float2(cs.x, 0.f);  R[1] = make_float2(0.f, -cs.y);
                R[2] = make_float2(0.f, -cs.y); R[3] = make_float2(cs.x, 0.f);
            } else if (br == 1) { // RY
                R[0] = make_float2(cs.x, 0.f);  R[1] = make_float2(-cs.y, 0.f);
                R[2] = make_float2(cs.y, 0.f);  R[3] = make_float2(cs.x, 0.f);
            } else {              // RZ
                R[0] = make_float2(cs.x, -cs.y); R[1] = make_float2(0.f, 0.f);
                R[2] = make_float2(0.f, 0.f);    R[3] = make_float2(cs.x, cs.y);
            }
            const float2* U = (which == 0) ? su3[br][1] : su3[br][3];
            float2* D = M[3 + which * 2];  // M[3]=MA1, M[5]=MB1
            D[0] = make_float2(cmul(R[0],U[0]).x + cmul(R[1],U[2]).x,
                               cmul(R[0],U[0]).y + cmul(R[1],U[2]).y);
            D[1] = make_float2(cmul(R[0],U[1]).x + cmul(R[1],U[3]).x,
                               cmul(R[0],U[1]).y + cmul(R[1],U[3]).y);
            D[2] = make_float2(cmul(R[2],U[0]).x + cmul(R[3],U[2]).x,
                               cmul(R[2],U[0]).y + cmul(R[3],U[2]).y);
            D[3] = make_float2(cmul(R[2],U[1]).x + cmul(R[3],U[3]).x,
                               cmul(R[2],U[1]).y + cmul(R[3],U[3]).y);
        }
        // pack dup'd coefficients
        for (int g = 0; g < 6; g++)
            for (int e = 0; e < 4; e++) {
                float2 E = M[g][e];
                g_mat[br][g][e*2+0] = make_float2(E.x, E.x);
                g_mat[br][g][e*2+1] = make_float2(-E.y, E.y);
            }
        // folded observables M = U^dag Z U for U3(3)' (su3[br][4]) and U3(7)' (su3[br][5])
        for (int w = 0; w < 2; w++) {
            const float2* U = su3[br][4 + w];
            float a = fmaf(U[0].x, U[0].x, U[0].y * U[0].y)
                    - fmaf(U[2].x, U[2].x, U[2].y * U[2].y);
            float2 b0 = cjmul(U[0], U[1]);
            float2 b1 = cjmul(U[2], U[3]);
            float2 b = make_float2(b0.x - b1.x, b0.y - b1.y);
            g_obs[br][w] = make_float4(a, 2.f * b.x, -2.f * b.y, 0.f);
        }
    }
}

// ---------------------------------------------------------------------------
// Gate primitives (packed).
// Bit layout: lane bits l4=q0(16) l3=q1(8) l2=q2(4) l1=q4(2) l0=q6(1);
// local bits  j2=q3(4) j1=q5(2) j0=q7(1).
// ---------------------------------------------------------------------------
static __device__ __forceinline__ void mat_pair(const float2* __restrict__ K,
                                                float2& x0, float2& x1) {
    float2 a0 = x0, a1 = x1, a0s = swp(a0), a1s = swp(a1);
    float2 o0 = f2mul(K[0], a0);
    o0 = f2fma(K[1], a0s, o0);
    o0 = f2fma(K[2], a1, o0);
    o0 = f2fma(K[3], a1s, o0);
    float2 o1 = f2mul(K[4], a0);
    o1 = f2fma(K[5], a0s, o1);
    o1 = f2fma(K[6], a1, o1);
    o1 = f2fma(K[7], a1s, o1);
    x0 = o0; x1 = o1;
}

static __device__ __forceinline__ void u3p_local(float2 s[8], const float2* __restrict__ K, int tm) {
#pragma unroll
    for (int j = 0; j < 8; j++) {
        if (j & tm) continue;
        mat_pair(K, s[j], s[j | tm]);
    }
}

static __device__ __forceinline__ void u3p_lane(float2 s[8], const float2* __restrict__ K,
                                                unsigned lm, bool hi) {
    const float2* Kd = K + (hi ? 6 : 0);
    const float2* Ko = K + (hi ? 4 : 2);
#pragma unroll
    for (int j = 0; j < 8; j++) {
        float px = __shfl_xor_sync(FULL, s[j].x, lm);
        float py = __shfl_xor_sync(FULL, s[j].y, lm);
        float2 p = make_float2(px, py);
        float2 o = f2mul(Kd[0], s[j]);
        o = f2fma(Kd[1], swp(s[j]), o);
        o = f2fma(Ko[0], p, o);
        o = f2fma(Ko[1], swp(p), o);
        s[j] = o;
    }
}

// CRX on a lane target: out = dup(c)*s + (s,-s)*(p.y,p.x); only j&jc rows active
static __device__ __forceinline__ void crx_lane_pk(float2 s[8], float2 kc, float2 ks,
                                                   unsigned lm, int jc) {
#pragma unroll
    for (int j = 0; j < 8; j++) {
        if ((j & jc) != jc) continue;
        float px = __shfl_xor_sync(FULL, s[j].x, lm);
        float py = __shfl_xor_sync(FULL, s[j].y, lm);
        float2 o = f2mul(kc, s[j]);
        s[j] = f2fma(ks, make_float2(py, px), o);
    }
}

// CRY on a lane target, REAL packed state rp[k]=(r[2k],r[2k+1]); kreg mask selects j regs
static __device__ __forceinline__ void cry_lane_rp(float2 rp[4], float2 kc, float2 ksgn,
                                                   unsigned lm, int kmask) {
#pragma unroll
    for (int k = 0; k < 4; k++) {
        if ((k & kmask) != kmask) continue;
        float px = __shfl_xor_sync(FULL, rp[k].x, lm);
        float py = __shfl_xor_sync(FULL, rp[k].y, lm);
        rp[k] = f2fma(ksgn, make_float2(px, py), f2mul(kc, rp[k]));
    }
}

// Measure folded observables M3 (on j2) and M7 (on j0) and warp-reduce.
// o3 = (a3, 2b3.x, -2b3.y, _), o7 likewise.
static __device__ __forceinline__ void obs_eval(const float2 s[8], float4 o3, float4 o7,
                                                float* e3o, float* e7o) {
    float p[8];
#pragma unroll
    for (int j = 0; j < 8; j++) {
        float2 q = f2mul(s[j], s[j]);
        p[j] = q.x + q.y;
    }
    float e3 = 0.f, e7 = 0.f;
#pragma unroll
    for (int j = 0; j < 4; j++) {          // pairs (j, j+4) across j2
        float2 a = s[j], b = s[j + 4];
        float tx = fmaf(a.x, b.x,  a.y * b.y);
        float ty = fmaf(a.x, b.y, -a.y * b.x);
        e3 = fmaf(o3.x, p[j] - p[j + 4], e3);
        e3 = fmaf(o3.y, tx, e3);
        e3 = fmaf(o3.z, ty, e3);
    }
#pragma unroll
    for (int k = 0; k < 4; k++) {          // pairs (2k, 2k+1) across j0
        float2 a = s[2 * k], b = s[2 * k + 1];
        float tx = fmaf(a.x, b.x,  a.y * b.y);
        float ty = fmaf(a.x, b.y, -a.y * b.x);
        e7 = fmaf(o7.x, p[2 * k] - p[2 * k + 1], e7);
        e7 = fmaf(o7.y, tx, e7);
        e7 = fmaf(o7.z, ty, e7);
    }
#pragma unroll
    for (int o = 16; o > 0; o >>= 1) {
        e3 += __shfl_xor_sync(FULL, e3, o);
        e7 += __shfl_xor_sync(FULL, e7, o);
    }
    *e3o = e3; *e7o = e7;
}

// shared tail per branch: U3(5), A(j2, lane-sel l3), B(j0, j1-sel)
static __device__ __forceinline__ void tail_a_b(float2 s[8], const float2* __restrict__ KM, bool L3) {
    u3p_local(s, KM + 8, 2);                        // U3(5) on j1
    u3p_local(s, KM + 16 + (L3 ? 8 : 0), 4);        // A on j2 (lane-selected)
    mat_pair(KM + 32, s[0], s[1]);                  // B on j0, j1=0
    mat_pair(KM + 40, s[2], s[3]);                  // j1=1
    mat_pair(KM + 32, s[4], s[5]);
    mat_pair(KM + 40, s[6], s[7]);
}

// ---------------------------------------------------------------------------
// Main kernel: one warp per batch element.
// ---------------------------------------------------------------------------
__global__ void __launch_bounds__(256, 4) qcnn_main(const float* __restrict__ x,
                                                    const float* __restrict__ w1,
                                                    const float* __restrict__ b1,
                                                    const float* __restrict__ w2,
                                                    const float* __restrict__ b2,
                                                    float* __restrict__ out, int batch) {
    __shared__ float2 s_mat[3][6][8];   // 144 float2
    __shared__ float4 s_obs[3][2];
    __shared__ float2 s_cr[3][10];
    __shared__ float  s_hz[8];
    __shared__ float  smw1[72];
    __shared__ float  smb1[12];
    __shared__ float  smw2[12];
    __shared__ float  smb2;

    {
        float2* d = &s_mat[0][0][0];
        const float2* g = &g_mat[0][0][0];
        for (int i = threadIdx.x; i < 144; i += blockDim.x) d[i] = g[i];
        for (int i = threadIdx.x; i < 72; i += blockDim.x) smw1[i] = w1[i];
        if (threadIdx.x < 30) ((float2*)s_cr)[threadIdx.x] = ((const float2*)g_cr)[threadIdx.x];
        if (threadIdx.x >= 32 && threadIdx.x < 39) s_hz[threadIdx.x - 32] = g_hz[threadIdx.x - 32];
        if (threadIdx.x >= 40 && threadIdx.x < 46)
            ((float4*)s_obs)[threadIdx.x - 40] = ((const float4*)g_obs)[threadIdx.x - 40];
        if (threadIdx.x >= 64 && threadIdx.x < 76) {
            smb1[threadIdx.x - 64] = b1[threadIdx.x - 64];
            smw2[threadIdx.x - 64] = w2[threadIdx.x - 64];
        }
        if (threadIdx.x == 0) smb2 = b2[0];
    }
    __syncthreads();

    int warp = (blockIdx.x * blockDim.x + threadIdx.x) >> 5;
    int lane = threadIdx.x & 31;
    if (warp >= batch) return;

    bool L4 = (lane & 16) != 0, L3 = (lane & 8) != 0, L2 = (lane & 4) != 0,
         L1 = (lane & 2) != 0,  L0 = (lane & 1) != 0;

    // ---- per-qubit (cos, sin) broadcast -----------------------------------
    float xv = 0.f;
    if (lane < 8) xv = x[warp * 8 + lane];
    float sv0, cv0;
    __sincosf(0.5f * xv, &sv0, &cv0);
    float cq[8], sq[8];
#pragma unroll
    for (int q = 0; q < 8; q++) {
        cq[q] = __shfl_sync(FULL, cv0, q);
        sq[q] = __shfl_sync(FULL, sv0, q);
    }
    float u0 = L4 ? sq[0] : cq[0];
    float u2 = L2 ? sq[2] : cq[2];
    float u4 = L1 ? sq[4] : cq[4];
    float u6 = L0 ? sq[6] : cq[6];
    float a1v = L3 ? sq[1] : cq[1];

    float feats[6];

    // ================= RX branch =================
    {
        const float2* cr = s_cr[0];
        const float2* KM = &s_mat[0][0][0];
        // fused encode + first CR layer (factor products)
        float a1w = L3 ? cq[1] : sq[1];
        float2 f01 = make_float2(u0 * (L4 ? cr[0].x * a1v : a1v),
                                 L4 ? -(u0 * cr[0].y * a1w) : 0.f);
        float cc1 = L2 ? cr[1].x : 1.f, ss1 = L2 ? cr[1].y : 0.f;
        float2 f23a = make_float2(u2 * cc1 * cq[3], -u2 * ss1 * sq[3]);
        float2 f23b = make_float2(u2 * cc1 * sq[3], -u2 * ss1 * cq[3]);
        float cc2 = L1 ? cr[2].x : 1.f, ss2 = L1 ? cr[2].y : 0.f;
        float2 f45a = make_float2(u4 * cc2 * cq[5], -u4 * ss2 * sq[5]);
        float2 f45b = make_float2(u4 * cc2 * sq[5], -u4 * ss2 * cq[5]);
        float cc3 = L0 ? cr[3].x : 1.f, ss3 = L0 ? cr[3].y : 0.f;
        float2 f67a = make_float2(u6 * cc3 * cq[7], -u6 * ss3 * sq[7]);
        float2 f67b = make_float2(u6 * cc3 * sq[7], -u6 * ss3 * cq[7]);
        float2 g0 = cmul(f01, f23a), g1 = cmul(f01, f23b);
        float2 h00 = cmul(f45a, f67a), h01 = cmul(f45a, f67b);
        float2 h10 = cmul(f45b, f67a), h11 = cmul(f45b, f67b);
        float2 s[8];
        {
            float2 kx = dup(g0.x), ky = make_float2(-g0.y, g0.y);
            s[0] = f2fma(ky, swp(h00), f2mul(kx, h00));
            s[1] = f2fma(ky, swp(h01), f2mul(kx, h01));
            s[2] = f2fma(ky, swp(h10), f2mul(kx, h10));
            s[3] = f2fma(ky, swp(h11), f2mul(kx, h11));
            kx = dup(g1.x); ky = make_float2(-g1.y, g1.y);
            s[4] = f2fma(ky, swp(h00), f2mul(kx, h00));
            s[5] = f2fma(ky, swp(h01), f2mul(kx, h01));
            s[6] = f2fma(ky, swp(h10), f2mul(kx, h10));
            s[7] = f2fma(ky, swp(h11), f2mul(kx, h11));
        }
        // remaining pairs1 lane gates
        {
            float cc = L3 ? cr[4].x : 1.f, ss = L3 ? cr[4].y : 0.f;
            crx_lane_pk(s, dup(cc), make_float2(ss, -ss), 4u, 0);   // CR(1,2)
        }
        crx_lane_pk(s, dup(cr[5].x), make_float2(cr[5].y, -cr[5].y), 2u, 4); // CR(3,4)
        crx_lane_pk(s, dup(cr[6].x), make_float2(cr[6].y, -cr[6].y), 1u, 2); // CR(5,6)
        u3p_lane(s, KM, 8u, L3);                                    // U3(1)
        tail_a_b(s, KM, L3);
        // CR(3,5): pairs (4,6),(5,7)
        {
            float2 kc = dup(cr[9].x), ks = make_float2(cr[9].y, -cr[9].y);
            float2 o4 = f2fma(ks, swp(s[6]), f2mul(kc, s[4]));
            float2 o6 = f2fma(ks, swp(s[4]), f2mul(kc, s[6]));
            float2 o5 = f2fma(ks, swp(s[7]), f2mul(kc, s[5]));
            float2 o7 = f2fma(ks, swp(s[5]), f2mul(kc, s[7]));
            s[4] = o4; s[6] = o6; s[5] = o5; s[7] = o7;
        }
        obs_eval(s, s_obs[0][0], s_obs[0][1], &feats[0], &feats[1]);
    }

    // ================= RY branch (pairs1 fully real) =================
    {
        const float2* cr = s_cr[1];
        const float2* KM = &s_mat[1][0][0];
        // fused encode + first CR layer, real factors
        float r1 = L3 ? fmaf(cr[0].y, cq[1], cr[0].x * sq[1])
                      : fmaf(cr[0].x, cq[1], -cr[0].y * sq[1]);
        float f01r = u0 * (L4 ? r1 : a1v);
        float cc1 = L2 ? cr[1].x : 1.f, ss1 = L2 ? cr[1].y : 0.f;
        float f23r0 = u2 * fmaf(cc1, cq[3], -ss1 * sq[3]);
        float f23r1 = u2 * fmaf(ss1, cq[3],  cc1 * sq[3]);
        float cc2 = L1 ? cr[2].x : 1.f, ss2 = L1 ? cr[2].y : 0.f;
        float f45r0 = u4 * fmaf(cc2, cq[5], -ss2 * sq[5]);
        float f45r1 = u4 * fmaf(ss2, cq[5],  cc2 * sq[5]);
        float cc3 = L0 ? cr[3].x : 1.f, ss3 = L0 ? cr[3].y : 0.f;
        float f67r0 = u6 * fmaf(cc3, cq[7], -ss3 * sq[7]);
        float f67r1 = u6 * fmaf(ss3, cq[7],  cc3 * sq[7]);
        float g0r = f01r * f23r0, g1r = f01r * f23r1;
        float2 hp0 = make_float2(f45r0 * f67r0, f45r0 * f67r1);
        float2 hp1 = make_float2(f45r1 * f67r0, f45r1 * f67r1);
        float2 rp[4];
        rp[0] = f2mul(dup(g0r), hp0);
        rp[1] = f2mul(dup(g0r), hp1);
        rp[2] = f2mul(dup(g1r), hp0);
        rp[3] = f2mul(dup(g1r), hp1);
        // remaining pairs1 lane gates on real packed state
        {
            float cc = L3 ? cr[4].x : 1.f, ss = L3 ? cr[4].y : 0.f;
            cry_lane_rp(rp, dup(cc), dup(L2 ? ss : -ss), 4u, 0);   // CR(1,2)
        }
        cry_lane_rp(rp, dup(cr[5].x), dup(L1 ? cr[5].y : -cr[5].y), 2u, 2); // CR(3,4)
        cry_lane_rp(rp, dup(cr[6].x), dup(L0 ? cr[6].y : -cr[6].y), 1u, 1); // CR(5,6)
        // U3(1) on real state -> complex
        float2 s[8];
        {
            const float2* K = KM;
            int di = L3 ? 3 : 0, oi = L3 ? 2 : 1;
            float2 cd = make_float2(K[di*2].x, K[di*2+1].y);
            float2 co = make_float2(K[oi*2].x, K[oi*2+1].y);
#pragma unroll
            for (int j = 0; j < 8; j++) {
                float r = (j & 1) ? rp[j >> 1].y : rp[j >> 1].x;
                float p = __shfl_xor_sync(FULL, r, 8);
                s[j] = f2fma(co, dup(p), f2mul(cd, dup(r)));
            }
        }
        tail_a_b(s, KM, L3);
        // CR(3,5): real coeffs, pairs (4,6),(5,7)
        {
            float2 kc = dup(cr[9].x), kn = dup(-cr[9].y), kp = dup(cr[9].y);
            float2 o4 = f2fma(kn, s[6], f2mul(kc, s[4]));
            float2 o6 = f2fma(kp, s[4], f2mul(kc, s[6]));
            float2 o5 = f2fma(kn, s[7], f2mul(kc, s[5]));
            float2 o7 = f2fma(kp, s[5], f2mul(kc, s[7]));
            s[4] = o4; s[6] = o6; s[5] = o5; s[7] = o7;
        }
        obs_eval(s, s_obs[1][0], s_obs[1][1], &feats[2], &feats[3]);
    }

    // ================= RZ branch =================
    {
        const float2* KM = &s_mat[2][0][0];
        // real product init
        float A = u0 * (L3 ? sq[1] : cq[1]) * u2 * u4 * u6;
        float init[8];
#pragma unroll
        for (int j = 0; j < 8; j++) {
            init[j] = A * ((j & 4) ? sq[3] : cq[3])
                        * ((j & 2) ? sq[5] : cq[5])
                        * ((j & 1) ? sq[7] : cq[7]);
        }
        // pairs1: 7 commuting diagonal CRZ -> single phase per amplitude
        float th_lane = 0.f;
        if (lane & 16) th_lane += (lane & 8) ? s_hz[0] : -s_hz[0];  // CR(0,1)
        if (lane & 8)  th_lane += (lane & 4) ? s_hz[4] : -s_hz[4];  // CR(1,2)
        float t1 = L2 ? s_hz[1] : 0.f;                              // CR(2,3)
        float t2 = L1 ? s_hz[2] : 0.f;                              // CR(4,5)
        float t3 = L0 ? s_hz[3] : 0.f;                              // CR(6,7)
        float u5 = L1 ? s_hz[5] : -s_hz[5];                         // CR(3,4)
        float u6z = L0 ? s_hz[6] : -s_hz[6];                        // CR(5,6)
        float2 s[8];
#pragma unroll
        for (int j = 0; j < 8; j++) {
            float th = th_lane
                     + ((j & 4) ? t1 : -t1)
                     + ((j & 2) ? t2 : -t2)
                     + ((j & 1) ? t3 : -t3);
            if (j & 4) th += u5;
            if (j & 2) th += u6z;
            float sn, cs;
            __sincosf(th, &sn, &cs);
            s[j] = f2mul(dup(init[j]), make_float2(cs, sn));
        }
        u3p_lane(s, KM, 8u, L3);                                    // U3(1)
        tail_a_b(s, KM, L3);
        // CR(3,5): diagonal phase: amps 4,5 *= e^{-ih9}; amps 6,7 *= e^{+ih9}
        {
            float2 cs9 = s_cr[2][9];
            float2 kc = dup(cs9.x);
            float2 km = make_float2(cs9.y, -cs9.y);
            float2 kp = make_float2(-cs9.y, cs9.y);
            s[4] = f2fma(km, swp(s[4]), f2mul(kc, s[4]));
            s[5] = f2fma(km, swp(s[5]), f2mul(kc, s[5]));
            s[6] = f2fma(kp, swp(s[6]), f2mul(kc, s[6]));
            s[7] = f2fma(kp, swp(s[7]), f2mul(kc, s[7]));
        }
        obs_eval(s, s_obs[2][0], s_obs[2][1], &feats[4], &feats[5]);
    }

    // ---- MLP ----------------------------------------------------------------
    float term = 0.f;
    if (lane < 12) {
        float z = smb1[lane];
#pragma unroll
        for (int j = 0; j < 6; j++) z = fmaf(smw1[lane * 6 + j], feats[j], z);
        term = smw2[lane] * tanhf(z);
    }
#pragma unroll
    for (int o = 8; o > 0; o >>= 1) term += __shfl_xor_sync(FULL, term, o);
    if (lane == 0) {
        float z2 = smb2 + term;
        out[warp] = 1.f / (1.f + expf(-z2));
    }
}

extern "C" void kernel_launch(void* const* d_in, const int* in_sizes, int n_in,
                              void* d_out, int out_size) {
    const float* x   = (const float*)d_in[0];
    const float* crx = (const float*)d_in[1];
    const float* u3x = (const float*)d_in[2];
    const float* cry = (const float*)d_in[3];
    const float* u3y = (const float*)d_in[4];
    const float* crz = (const float*)d_in[5];
    const float* u3z = (const float*)d_in[6];
    const float* w1  = (const float*)d_in[7];
    const float* b1  = (const float*)d_in[8];
    const float* w2  = (const float*)d_in[9];
    const float* b2  = (const float*)d_in[10];
    float* out = (float*)d_out;

    int batch = in_sizes[0] / NQ;

    qcnn_precompute<<<1, 64>>>(crx, u3x, cry, u3y, crz, u3z);

    int threads = 256;   // 8 warps per block
    int blocks = (batch * 32 + threads - 1) / threads;
    qcnn_main<<<blocks, threads>>>(x, w1, b1, w2, b2, out, batch);
}